// round 2
// baseline (speedup 1.0000x reference)
#include <cuda_runtime.h>
#include <cstddef>

#define S_LEN 256
#define BATCH 256
#define HID   512
#define OUTD  64
#define NSTEP 63
#define KCAT  1088   // 64 (x) + 512 (ctx) + 512 (h)

// ---------------- scratch (device globals: allocation-free rule) ----------------
__device__ float g_P[(size_t)S_LEN * BATCH * HID];   // 134 MB: P[s*B+b][h] = enc@Wa_enc + ba
__device__ float g_q[BATCH * HID];
__device__ float g_score[BATCH * S_LEN];             // [b][s]
__device__ float g_rin[BATCH * KCAT];                // [x | ctx | h]
__device__ float g_WcatT[KCAT * HID];                // [k][h] transposed concat of W_ih^T, W_hh^T
__device__ float g_bsum[HID];                        // b_ih + b_hh
__device__ float g_h0buf[BATCH * HID];
__device__ float g_h1buf[BATCH * HID];
__device__ float g_x0buf[BATCH * OUTD];
__device__ float g_x1buf[BATCH * OUTD];

// Accurate-enough tanh (~1e-7 abs): tanh(x) = 1 - 2/(exp(2x)+1). Handles +-inf cleanly.
__device__ __forceinline__ float fast_tanh(float x) {
    float e = __expf(2.0f * x);
    return 1.0f - __fdividef(2.0f, e + 1.0f);
}

// ---------------- generic fp32 tiled GEMM: C = act(A(MxK) * B(KxN,row-major) + bias) ----
// 64x64 CTA tile, 256 threads, 4x4 per-thread microtile. M%64==0, N%64==0, K%16==0.
template <int ACT>
__global__ void gemm64(const float* __restrict__ A, const float* __restrict__ B,
                       const float* __restrict__ bias, float* __restrict__ C,
                       int M, int N, int K) {
    __shared__ __align__(16) float As[16][68];   // transposed: As[k][m], padded
    __shared__ __align__(16) float Bs[16][64];
    int t  = threadIdx.x;
    int tx = t & 15, ty = t >> 4;
    int m0 = blockIdx.x * 64, n0 = blockIdx.y * 64;

    float acc[4][4];
#pragma unroll
    for (int j = 0; j < 4; j++) {
        float bv = bias ? bias[n0 + tx * 4 + j] : 0.0f;
#pragma unroll
        for (int i = 0; i < 4; i++) acc[i][j] = bv;
    }

    int arow = t >> 2, akq = (t & 3) * 4;
    int bk = t >> 4, bn = (t & 15) * 4;

    for (int kc = 0; kc < K; kc += 16) {
        float4 av = *(const float4*)(A + (size_t)(m0 + arow) * K + kc + akq);
        As[akq + 0][arow] = av.x;
        As[akq + 1][arow] = av.y;
        As[akq + 2][arow] = av.z;
        As[akq + 3][arow] = av.w;
        *(float4*)(&Bs[bk][bn]) = *(const float4*)(B + (size_t)(kc + bk) * N + n0 + bn);
        __syncthreads();
#pragma unroll
        for (int kk = 0; kk < 16; kk++) {
            float4 a = *(const float4*)(&As[kk][ty * 4]);
            float4 b = *(const float4*)(&Bs[kk][tx * 4]);
            float aa[4] = {a.x, a.y, a.z, a.w};
            float bb[4] = {b.x, b.y, b.z, b.w};
#pragma unroll
            for (int i = 0; i < 4; i++)
#pragma unroll
                for (int j = 0; j < 4; j++) acc[i][j] += aa[i] * bb[j];
        }
        __syncthreads();
    }

#pragma unroll
    for (int i = 0; i < 4; i++) {
        float r0 = acc[i][0], r1 = acc[i][1], r2 = acc[i][2], r3 = acc[i][3];
        if (ACT) { r0 = fast_tanh(r0); r1 = fast_tanh(r1); r2 = fast_tanh(r2); r3 = fast_tanh(r3); }
        float4 o = make_float4(r0, r1, r2, r3);
        *(float4*)(C + (size_t)(m0 + ty * 4 + i) * N + n0 + tx * 4) = o;
    }
}

// ---------------- one-time setup kernels ----------------
__global__ void build_wcat(const float* __restrict__ W_ih, const float* __restrict__ W_hh,
                           const float* __restrict__ b_ih, const float* __restrict__ b_hh) {
    int idx = blockIdx.x * 256 + threadIdx.x;
    if (idx < KCAT * HID) {
        int k = idx / HID, h = idx - k * HID;
        float w = (k < 576) ? W_ih[(size_t)h * 576 + k] : W_hh[(size_t)h * 512 + (k - 576)];
        g_WcatT[idx] = w;
    }
    if (idx < HID) g_bsum[idx] = b_ih[idx] + b_hh[idx];
}

__global__ void init_state(const float* __restrict__ h0, const float* __restrict__ x0) {
    int i = blockIdx.x * 256 + threadIdx.x;
    if (i < BATCH * HID) g_h0buf[i] = h0[i];
    if (i < BATCH * OUTD) g_x0buf[i] = x0[i];
}

// ---------------- score: score[b][s] = sum_h tanh(P[s,b,h] + q[b,h]) * v[h] ----------------
// grid (32, 256): x = s-chunk of 8 (one s per warp), y = b. 256 threads.
__global__ void score_kernel(const float* __restrict__ v) {
    __shared__ __align__(16) float sq[HID];
    __shared__ __align__(16) float sv[HID];
    int b = blockIdx.y, t = threadIdx.x;
    sq[t] = g_q[b * HID + t];
    sq[t + 256] = g_q[b * HID + t + 256];
    sv[t] = v[t];
    sv[t + 256] = v[t + 256];
    __syncthreads();

    int warp = t >> 5, lane = t & 31;
    int s = blockIdx.x * 8 + warp;
    const float4* Pr = (const float4*)(g_P + (size_t)(s * BATCH + b) * HID);
    const float4* q4 = (const float4*)sq;
    const float4* v4 = (const float4*)sv;
    float acc = 0.0f;
#pragma unroll
    for (int i = 0; i < 4; i++) {
        int h4 = i * 32 + lane;
        float4 p = Pr[h4], q = q4[h4], vv = v4[h4];
        acc += fast_tanh(p.x + q.x) * vv.x + fast_tanh(p.y + q.y) * vv.y +
               fast_tanh(p.z + q.z) * vv.z + fast_tanh(p.w + q.w) * vv.w;
    }
#pragma unroll
    for (int o = 16; o; o >>= 1) acc += __shfl_xor_sync(0xffffffffu, acc, o);
    if (lane == 0) g_score[b * S_LEN + s] = acc;
}

// ---------------- softmax over s + context, pack rnn_in = [x, ctx, h] ----------------
// grid 256 (b), 256 threads (one per s; thread also owns h = t, t+256 for ctx).
__global__ void ctx_kernel(const float* __restrict__ enc, const float* __restrict__ xin,
                           const float* __restrict__ hin) {
    int b = blockIdx.x, t = threadIdx.x;
    __shared__ float sa[S_LEN];
    __shared__ float red[8];

    float sc = g_score[b * S_LEN + t];
    float m = sc;
#pragma unroll
    for (int o = 16; o; o >>= 1) m = fmaxf(m, __shfl_xor_sync(0xffffffffu, m, o));
    if ((t & 31) == 0) red[t >> 5] = m;
    __syncthreads();
    if (t < 8) {
        m = red[t];
#pragma unroll
        for (int o = 4; o; o >>= 1) m = fmaxf(m, __shfl_xor_sync(0xffu, m, o));
        red[t] = m;
    }
    __syncthreads();
    m = red[0];

    float e = __expf(sc - m);
    sa[t] = e;
    float ssum = e;
#pragma unroll
    for (int o = 16; o; o >>= 1) ssum += __shfl_xor_sync(0xffffffffu, ssum, o);
    __syncthreads();                       // everyone has read red[0]; sa is written
    if ((t & 31) == 0) red[t >> 5] = ssum;
    __syncthreads();
    if (t < 8) {
        ssum = red[t];
#pragma unroll
        for (int o = 4; o; o >>= 1) ssum += __shfl_xor_sync(0xffu, ssum, o);
        red[t] = ssum;
    }
    __syncthreads();
    float inv = __fdividef(1.0f, red[0]);

    float c0 = 0.0f, c1 = 0.0f;
#pragma unroll 4
    for (int s = 0; s < S_LEN; s++) {
        float a = sa[s];
        const float* row = enc + (size_t)(s * BATCH + b) * HID;
        c0 += a * row[t];
        c1 += a * row[t + 256];
    }
    c0 *= inv;
    c1 *= inv;
    g_rin[b * KCAT + OUTD + t] = c0;
    g_rin[b * KCAT + OUTD + t + 256] = c1;
    if (t < OUTD) g_rin[b * KCAT + t] = xin[b * OUTD + t];
    g_rin[b * KCAT + 576 + t] = hin[b * HID + t];
    g_rin[b * KCAT + 576 + t + 256] = hin[b * HID + t + 256];
}

// ---------------- output head + argmax + one-hot feedback ----------------
// grid 256 (b), 256 threads (8 warps x 8 classes).
__global__ void out_kernel(const float* __restrict__ Wo, const float* __restrict__ bo,
                           const float* __restrict__ hnew, float* __restrict__ dout,
                           float* __restrict__ xnext, int step) {
    int b = blockIdx.x, t = threadIdx.x;
    __shared__ __align__(16) float sh[HID];
    __shared__ float so[OUTD];
    __shared__ int sbest;
    sh[t] = hnew[b * HID + t];
    sh[t + 256] = hnew[b * HID + t + 256];
    __syncthreads();

    int warp = t >> 5, lane = t & 31;
    const float4* h4 = (const float4*)sh;
    for (int o = warp; o < OUTD; o += 8) {
        const float4* w4 = (const float4*)(Wo + (size_t)o * HID);
        float acc = 0.0f;
#pragma unroll
        for (int i = 0; i < 4; i++) {
            float4 w = w4[i * 32 + lane], h = h4[i * 32 + lane];
            acc += w.x * h.x + w.y * h.y + w.z * h.z + w.w * h.w;
        }
#pragma unroll
        for (int off = 16; off; off >>= 1) acc += __shfl_xor_sync(0xffffffffu, acc, off);
        if (lane == 0) so[o] = acc + bo[o];
    }
    __syncthreads();
    if (t < OUTD) dout[((size_t)b * OUTD + t) * NSTEP + step] = so[t];
    if (t == 0) {
        float best = so[0];
        int bi = 0;
#pragma unroll
        for (int o = 1; o < OUTD; o++)
            if (so[o] > best) { best = so[o]; bi = o; }   // first-max, matches jnp.argmax
        sbest = bi;
    }
    __syncthreads();
    if (t < OUTD) xnext[b * OUTD + t] = (t == sbest) ? 1.0f : 0.0f;
}

// ---------------- launch ----------------
extern "C" void kernel_launch(void* const* d_in, const int* in_sizes, int n_in,
                              void* d_out, int out_size) {
    const float* sos = (const float*)d_in[0];
    const float* h0  = (const float*)d_in[1];
    const float* enc = (const float*)d_in[2];
    const float* Wa  = (const float*)d_in[3];
    const float* ba  = (const float*)d_in[4];
    const float* v   = (const float*)d_in[5];
    const float* Wih = (const float*)d_in[6];
    const float* bih = (const float*)d_in[7];
    const float* Whh = (const float*)d_in[8];
    const float* bhh = (const float*)d_in[9];
    const float* Wo  = (const float*)d_in[10];
    const float* bo  = (const float*)d_in[11];
    float* out = (float*)d_out;

    float *pP, *pq, *pr, *pW, *pb, *ph[2], *px[2];
    cudaGetSymbolAddress((void**)&pP, g_P);
    cudaGetSymbolAddress((void**)&pq, g_q);
    cudaGetSymbolAddress((void**)&pr, g_rin);
    cudaGetSymbolAddress((void**)&pW, g_WcatT);
    cudaGetSymbolAddress((void**)&pb, g_bsum);
    cudaGetSymbolAddress((void**)&ph[0], g_h0buf);
    cudaGetSymbolAddress((void**)&ph[1], g_h1buf);
    cudaGetSymbolAddress((void**)&px[0], g_x0buf);
    cudaGetSymbolAddress((void**)&px[1], g_x1buf);

    init_state<<<512, 256>>>(h0, sos);
    build_wcat<<<(KCAT * HID + 255) / 256, 256>>>(Wih, Whh, bih, bhh);
    // P = enc @ Wa[512:] + ba   (M=65536, N=512, K=512)
    gemm64<0><<<dim3(S_LEN * BATCH / 64, HID / 64), 256>>>(enc, Wa + 512 * HID, ba, pP,
                                                           S_LEN * BATCH, HID, HID);

    for (int t = 0; t < NSTEP; t++) {
        int cur = t & 1, nxt = cur ^ 1;
        // q = h_t @ Wa[:512]
        gemm64<0><<<dim3(BATCH / 64, HID / 64), 256>>>(ph[cur], Wa, nullptr, pq,
                                                       BATCH, HID, HID);
        score_kernel<<<dim3(S_LEN / 8, BATCH), 256>>>(v);
        ctx_kernel<<<BATCH, 256>>>(enc, px[cur], ph[cur]);
        // h_new = tanh(rnn_in @ WcatT + b_ih + b_hh)
        gemm64<1><<<dim3(BATCH / 64, HID / 64), 256>>>(pr, pW, pb, ph[nxt],
                                                       BATCH, HID, KCAT);
        out_kernel<<<BATCH, 256>>>(Wo, bo, ph[nxt], out, px[nxt], t);
    }
}

// round 3
// speedup vs baseline: 1.7617x; 1.7617x over previous
#include <cuda_runtime.h>
#include <cstddef>

#define S_LEN  256
#define BATCH  256
#define HID    512
#define OUTD   64
#define NSTEP  63
#define KCAT   1088   // 64 (x) + 512 (ctx) + 512 (h)
#define KPAD   1152   // padded: 8 splits * 144, 144 = 9*16
#define KSPLIT 8

// ---------------- scratch (device globals: allocation-free rule) ----------------
__device__ float g_P[(size_t)S_LEN * BATCH * HID];      // P[s*B+b][h] = enc@Wa_enc + ba
__device__ float g_qpart[KSPLIT * BATCH * HID];         // split-K partials of q
__device__ float g_rnnpart[KSPLIT * BATCH * HID];       // split-K partials of rnn gemm
__device__ float g_rin[BATCH * KPAD];                   // [x | ctx | h | 0-pad]
__device__ float g_WcatT[KPAD * HID];                   // [k][h]
__device__ float g_bsum[HID];
__device__ float g_h0buf[BATCH * HID];
__device__ float g_h1buf[BATCH * HID];
__device__ float g_x0buf[BATCH * OUTD];
__device__ float g_x1buf[BATCH * OUTD];

__device__ __forceinline__ float fast_tanh(float x) {
    float e = __expf(2.0f * x);
    return 1.0f - __fdividef(2.0f, e + 1.0f);
}

// ============== P precompute: 128x128 tile, 8x8 microtile, double-buffered ==============
// C = A(MxK) * B(KxN) + bias.  M%128==0, N%128==0, K%8==0.
__global__ void __launch_bounds__(256) gemm128(const float* __restrict__ A,
                                               const float* __restrict__ B,
                                               const float* __restrict__ bias,
                                               float* __restrict__ C,
                                               int M, int N, int K) {
    __shared__ float As[2][8][132];   // [buf][k][m], padded to kill store conflicts
    __shared__ float Bs[2][8][128];   // [buf][k][n]
    int t  = threadIdx.x;
    int tx = t & 15, ty = t >> 4;
    int m0 = blockIdx.x * 128, n0 = blockIdx.y * 128;

    int ar = t >> 1;            // A stage: row 0..127
    int ak = (t & 1) * 4;       // A stage: k-offset 0 or 4
    int br = t >> 5;            // B stage: k-row 0..7
    int bn = (t & 31) * 4;      // B stage: n-offset

    const float* Aptr = A + (size_t)(m0 + ar) * K + ak;
    const float* Bptr = B + (size_t)br * N + n0 + bn;

    float acc[8][8];
#pragma unroll
    for (int j = 0; j < 8; j++) {
        int n = (j < 4) ? tx * 4 + j : 64 + tx * 4 + (j - 4);
        float bv = bias ? bias[n0 + n] : 0.0f;
#pragma unroll
        for (int i = 0; i < 8; i++) acc[i][j] = bv;
    }

    // prologue: stage chunk 0
    float4 a_reg = *(const float4*)(Aptr);
    float4 b_reg = *(const float4*)(Bptr);
    As[0][ak + 0][ar] = a_reg.x;
    As[0][ak + 1][ar] = a_reg.y;
    As[0][ak + 2][ar] = a_reg.z;
    As[0][ak + 3][ar] = a_reg.w;
    *(float4*)(&Bs[0][br][bn]) = b_reg;
    __syncthreads();

    int nc = K / 8, buf = 0;
    for (int c = 0; c < nc; c++) {
        if (c + 1 < nc) {
            a_reg = *(const float4*)(Aptr + (c + 1) * 8);
            b_reg = *(const float4*)(Bptr + (size_t)(c + 1) * 8 * N);
        }
#pragma unroll
        for (int kk = 0; kk < 8; kk++) {
            float4 a0 = *(const float4*)(&As[buf][kk][ty * 4]);
            float4 a1 = *(const float4*)(&As[buf][kk][64 + ty * 4]);
            float4 b0 = *(const float4*)(&Bs[buf][kk][tx * 4]);
            float4 b1 = *(const float4*)(&Bs[buf][kk][64 + tx * 4]);
            float av[8] = {a0.x, a0.y, a0.z, a0.w, a1.x, a1.y, a1.z, a1.w};
            float bv[8] = {b0.x, b0.y, b0.z, b0.w, b1.x, b1.y, b1.z, b1.w};
#pragma unroll
            for (int i = 0; i < 8; i++)
#pragma unroll
                for (int j = 0; j < 8; j++) acc[i][j] += av[i] * bv[j];
        }
        if (c + 1 < nc) {
            int nb = buf ^ 1;
            As[nb][ak + 0][ar] = a_reg.x;
            As[nb][ak + 1][ar] = a_reg.y;
            As[nb][ak + 2][ar] = a_reg.z;
            As[nb][ak + 3][ar] = a_reg.w;
            *(float4*)(&Bs[nb][br][bn]) = b_reg;
        }
        __syncthreads();
        buf ^= 1;
    }

#pragma unroll
    for (int i = 0; i < 8; i++) {
        int m = m0 + ((i < 4) ? ty * 4 + i : 64 + ty * 4 + (i - 4));
        float4 o0 = make_float4(acc[i][0], acc[i][1], acc[i][2], acc[i][3]);
        float4 o1 = make_float4(acc[i][4], acc[i][5], acc[i][6], acc[i][7]);
        *(float4*)(C + (size_t)m * N + n0 + tx * 4) = o0;
        *(float4*)(C + (size_t)m * N + n0 + 64 + tx * 4) = o1;
    }
}

// ============== split-K skinny GEMM: Cpart[z] = A(M x klen slice) * B slice ==============
// 64x64 tile, 4x4 microtile, grid (M/64, N/64, KSPLIT).
template <int KLEN>
__global__ void __launch_bounds__(256) gemm64s(const float* __restrict__ A, int lda,
                                               const float* __restrict__ B,
                                               float* __restrict__ Cpart,
                                               int M, int N) {
    __shared__ __align__(16) float As[16][68];
    __shared__ __align__(16) float Bs[16][64];
    int t  = threadIdx.x;
    int tx = t & 15, ty = t >> 4;
    int m0 = blockIdx.x * 64, n0 = blockIdx.y * 64;
    int kbase = blockIdx.z * KLEN;

    float acc[4][4];
#pragma unroll
    for (int i = 0; i < 4; i++)
#pragma unroll
        for (int j = 0; j < 4; j++) acc[i][j] = 0.0f;

    int arow = t >> 2, akq = (t & 3) * 4;
    int bk = t >> 4, bn = (t & 15) * 4;

    for (int kc = kbase; kc < kbase + KLEN; kc += 16) {
        float4 av = *(const float4*)(A + (size_t)(m0 + arow) * lda + kc + akq);
        As[akq + 0][arow] = av.x;
        As[akq + 1][arow] = av.y;
        As[akq + 2][arow] = av.z;
        As[akq + 3][arow] = av.w;
        *(float4*)(&Bs[bk][bn]) = *(const float4*)(B + (size_t)(kc + bk) * N + n0 + bn);
        __syncthreads();
#pragma unroll
        for (int kk = 0; kk < 16; kk++) {
            float4 a = *(const float4*)(&As[kk][ty * 4]);
            float4 b = *(const float4*)(&Bs[kk][tx * 4]);
            float aa[4] = {a.x, a.y, a.z, a.w};
            float bb[4] = {b.x, b.y, b.z, b.w};
#pragma unroll
            for (int i = 0; i < 4; i++)
#pragma unroll
                for (int j = 0; j < 4; j++) acc[i][j] += aa[i] * bb[j];
        }
        __syncthreads();
    }

    float* Cp = Cpart + (size_t)blockIdx.z * M * N;
#pragma unroll
    for (int i = 0; i < 4; i++) {
        float4 o = make_float4(acc[i][0], acc[i][1], acc[i][2], acc[i][3]);
        *(float4*)(Cp + (size_t)(m0 + ty * 4 + i) * N + n0 + tx * 4) = o;
    }
}

// ---------------- one-time setup ----------------
__global__ void build_wcat(const float* __restrict__ W_ih, const float* __restrict__ W_hh,
                           const float* __restrict__ b_ih, const float* __restrict__ b_hh) {
    int idx = blockIdx.x * 256 + threadIdx.x;
    if (idx < KPAD * HID) {
        int k = idx / HID, h = idx - k * HID;
        float w = 0.0f;
        if (k < 576)       w = W_ih[(size_t)h * 576 + k];
        else if (k < KCAT) w = W_hh[(size_t)h * 512 + (k - 576)];
        g_WcatT[idx] = w;
    }
    if (idx < HID) g_bsum[idx] = b_ih[idx] + b_hh[idx];
}

__global__ void init_state(const float* __restrict__ h0, const float* __restrict__ x0) {
    int i = blockIdx.x * 256 + threadIdx.x;
    if (i < BATCH * HID) g_h0buf[i] = h0[i];
    if (i < BATCH * OUTD) g_x0buf[i] = x0[i];
    if (i < BATCH * (KPAD - KCAT))   // zero the rin K-pad region once per launch
        g_rin[(i >> 6) * KPAD + KCAT + (i & 63)] = 0.0f;
}

// ============== fused: q-reduce + score + softmax + context + rnn_in pack ==============
// grid 256 (one block per b), 1024 threads.
__global__ void __launch_bounds__(1024) scorectx(const float* __restrict__ v,
                                                 const float* __restrict__ enc,
                                                 const float* __restrict__ xin,
                                                 const float* __restrict__ hin) {
    __shared__ __align__(16) float sq[HID];
    __shared__ __align__(16) float sv[HID];
    __shared__ float sa[S_LEN];
    __shared__ float sc[2][HID];
    __shared__ float red[32];

    int b = blockIdx.x, t = threadIdx.x;
    int warp = t >> 5, lane = t & 31;

    // q = sum of 8 split-K partials (fixed order -> deterministic)
    if (t < HID) {
        float s = 0.0f;
#pragma unroll
        for (int ks = 0; ks < KSPLIT; ks++)
            s += g_qpart[(size_t)ks * BATCH * HID + b * HID + t];
        sq[t] = s;
        sv[t] = v[t];
    }
    __syncthreads();

    // scores: 32 warps x 8 s each
    const float4* q4 = (const float4*)sq;
    const float4* v4 = (const float4*)sv;
#pragma unroll 2
    for (int i = 0; i < 8; i++) {
        int s = warp * 8 + i;
        const float4* Pr = (const float4*)(g_P + ((size_t)s * BATCH + b) * HID);
        float acc = 0.0f;
#pragma unroll
        for (int j = 0; j < 4; j++) {
            int h4 = j * 32 + lane;
            float4 p = Pr[h4], q = q4[h4], vv = v4[h4];
            acc += fast_tanh(p.x + q.x) * vv.x + fast_tanh(p.y + q.y) * vv.y +
                   fast_tanh(p.z + q.z) * vv.z + fast_tanh(p.w + q.w) * vv.w;
        }
#pragma unroll
        for (int o = 16; o; o >>= 1) acc += __shfl_xor_sync(0xffffffffu, acc, o);
        if (lane == 0) sa[s] = acc;
    }
    __syncthreads();

    // softmax over 256 scores (all 1024 threads participate with neutral pads)
    float scv = (t < S_LEN) ? sa[t] : -3.4e38f;
    float mx = scv;
#pragma unroll
    for (int o = 16; o; o >>= 1) mx = fmaxf(mx, __shfl_xor_sync(0xffffffffu, mx, o));
    if (lane == 0) red[warp] = mx;
    __syncthreads();
    if (t < 32) {
        float r = red[t];
#pragma unroll
        for (int o = 16; o; o >>= 1) r = fmaxf(r, __shfl_xor_sync(0xffffffffu, r, o));
        if (t == 0) red[0] = r;
    }
    __syncthreads();
    float m = red[0];
    float e = (t < S_LEN) ? __expf(scv - m) : 0.0f;
    float sm = e;
#pragma unroll
    for (int o = 16; o; o >>= 1) sm += __shfl_xor_sync(0xffffffffu, sm, o);
    __syncthreads();
    if (lane == 0) red[warp] = sm;
    __syncthreads();
    if (t < 32) {
        float r = red[t];
#pragma unroll
        for (int o = 16; o; o >>= 1) r += __shfl_xor_sync(0xffffffffu, r, o);
        if (t == 0) red[0] = r;
    }
    __syncthreads();
    float inv = __fdividef(1.0f, red[0]);
    if (t < S_LEN) sa[t] = e * inv;        // normalized attention weight
    __syncthreads();

    // context: thread t owns h = t&511, half = t>>9 covers 128 s values
    {
        int h = t & (HID - 1);
        int half = t >> 9;
        const float* ep = enc + ((size_t)(half * 128) * BATCH + b) * HID + h;
        const float* ap = sa + half * 128;
        float c = 0.0f;
#pragma unroll 4
        for (int s = 0; s < 128; s++)
            c += ap[s] * ep[(size_t)s * BATCH * HID];
        sc[half][h] = c;
    }
    __syncthreads();

    // pack rnn_in = [x | ctx | h]
    if (t < HID) {
        float ctx = sc[0][t] + sc[1][t];
        g_rin[b * KPAD + OUTD + t] = ctx;
        g_rin[b * KPAD + OUTD + HID + t] = hin[b * HID + t];
    }
    if (t < OUTD) g_rin[b * KPAD + t] = xin[b * OUTD + t];
}

// ============== reduce rnn partials + tanh + output head + argmax + one-hot ==============
// grid 256 (b), 256 threads.
__global__ void __launch_bounds__(256) outred(const float* __restrict__ Wo,
                                              const float* __restrict__ bo,
                                              float* __restrict__ hout,
                                              float* __restrict__ dout,
                                              float* __restrict__ xnext, int step) {
    int b = blockIdx.x, t = threadIdx.x;
    __shared__ __align__(16) float sh[HID];
    __shared__ float so[OUTD];
    __shared__ int sbest;

    float s0 = g_bsum[t], s1 = g_bsum[t + 256];
#pragma unroll
    for (int ks = 0; ks < KSPLIT; ks++) {
        const float* p = g_rnnpart + (size_t)ks * BATCH * HID + b * HID;
        s0 += p[t];
        s1 += p[t + 256];
    }
    float v0 = fast_tanh(s0), v1 = fast_tanh(s1);
    sh[t] = v0;
    sh[t + 256] = v1;
    hout[b * HID + t] = v0;
    hout[b * HID + t + 256] = v1;
    __syncthreads();

    int warp = t >> 5, lane = t & 31;
    const float4* h4 = (const float4*)sh;
    for (int o = warp; o < OUTD; o += 8) {
        const float4* w4 = (const float4*)(Wo + (size_t)o * HID);
        float acc = 0.0f;
#pragma unroll
        for (int i = 0; i < 4; i++) {
            float4 w = w4[i * 32 + lane], h = h4[i * 32 + lane];
            acc += w.x * h.x + w.y * h.y + w.z * h.z + w.w * h.w;
        }
#pragma unroll
        for (int off = 16; off; off >>= 1) acc += __shfl_xor_sync(0xffffffffu, acc, off);
        if (lane == 0) so[o] = acc + bo[o];
    }
    __syncthreads();
    if (t < OUTD) dout[((size_t)b * OUTD + t) * NSTEP + step] = so[t];
    if (t == 0) {
        float best = so[0];
        int bi = 0;
#pragma unroll
        for (int o = 1; o < OUTD; o++)
            if (so[o] > best) { best = so[o]; bi = o; }
        sbest = bi;
    }
    __syncthreads();
    if (t < OUTD) xnext[b * OUTD + t] = (t == sbest) ? 1.0f : 0.0f;
}

// ---------------- launch ----------------
extern "C" void kernel_launch(void* const* d_in, const int* in_sizes, int n_in,
                              void* d_out, int out_size) {
    const float* sos = (const float*)d_in[0];
    const float* h0  = (const float*)d_in[1];
    const float* enc = (const float*)d_in[2];
    const float* Wa  = (const float*)d_in[3];
    const float* ba  = (const float*)d_in[4];
    const float* v   = (const float*)d_in[5];
    const float* Wih = (const float*)d_in[6];
    const float* bih = (const float*)d_in[7];
    const float* Whh = (const float*)d_in[8];
    const float* bhh = (const float*)d_in[9];
    const float* Wo  = (const float*)d_in[10];
    const float* bo  = (const float*)d_in[11];
    float* out = (float*)d_out;

    float *pP, *pqp, *prp, *pr, *pW, *ph[2], *px[2];
    cudaGetSymbolAddress((void**)&pP,  g_P);
    cudaGetSymbolAddress((void**)&pqp, g_qpart);
    cudaGetSymbolAddress((void**)&prp, g_rnnpart);
    cudaGetSymbolAddress((void**)&pr,  g_rin);
    cudaGetSymbolAddress((void**)&pW,  g_WcatT);
    cudaGetSymbolAddress((void**)&ph[0], g_h0buf);
    cudaGetSymbolAddress((void**)&ph[1], g_h1buf);
    cudaGetSymbolAddress((void**)&px[0], g_x0buf);
    cudaGetSymbolAddress((void**)&px[1], g_x1buf);

    init_state<<<512, 256>>>(h0, sos);
    build_wcat<<<(KPAD * HID + 255) / 256, 256>>>(Wih, Whh, bih, bhh);
    // P = enc @ Wa[512:] + ba   (M=65536, N=512, K=512)
    gemm128<<<dim3(S_LEN * BATCH / 128, HID / 128), 256>>>(enc, Wa + 512 * HID, ba, pP,
                                                           S_LEN * BATCH, HID, HID);

    for (int t = 0; t < NSTEP; t++) {
        int cur = t & 1, nxt = cur ^ 1;
        // q partials = h_t @ Wa[:512], split-K 8x64
        gemm64s<64><<<dim3(BATCH / 64, HID / 64, KSPLIT), 256>>>(ph[cur], HID, Wa, pqp,
                                                                 BATCH, HID);
        scorectx<<<BATCH, 1024>>>(v, enc, px[cur], ph[cur]);
        // rnn partials = rnn_in @ WcatT, split-K 8x144 (padded)
        gemm64s<144><<<dim3(BATCH / 64, HID / 64, KSPLIT), 256>>>(pr, KPAD, pW, prp,
                                                                  BATCH, HID);
        outred<<<BATCH, 256>>>(Wo, bo, ph[nxt], out, px[nxt], t);
    }
}

// round 4
// speedup vs baseline: 1.7767x; 1.0085x over previous
#include <cuda_runtime.h>
#include <cstddef>

#define S_LEN  256
#define BATCH  256
#define HID    512
#define OUTD   64
#define NSTEP  63
#define KCAT   1088   // 64 (x) + 512 (ctx) + 512 (h)
#define KPAD   1152   // 8 splits * 144
#define KSPLIT 8

// ---------------- scratch (device globals: allocation-free rule) ----------------
__device__ float g_P[(size_t)S_LEN * BATCH * HID];      // P[s*B+b][h] = enc@Wa_enc + ba
__device__ float g_qpart[KSPLIT * BATCH * HID];
__device__ float g_rnnpart[KSPLIT * BATCH * HID];
__device__ float g_rin[BATCH * KPAD];                   // [x | ctx | h | 0-pad]
__device__ float g_WcatT[KPAD * HID];
__device__ float g_bsum[HID];
__device__ float g_h0buf[BATCH * HID];
__device__ float g_h1buf[BATCH * HID];
__device__ float g_x0buf[BATCH * OUTD];
__device__ float g_x1buf[BATCH * OUTD];

__device__ __forceinline__ float fast_tanh(float x) {
    float e = __expf(2.0f * x);
    return 1.0f - __fdividef(2.0f, e + 1.0f);
}

// ============== P precompute: 128x128 tile, 8x8 microtile, double-buffered ==============
__global__ void __launch_bounds__(256) gemm128(const float* __restrict__ A,
                                               const float* __restrict__ B,
                                               const float* __restrict__ bias,
                                               float* __restrict__ C,
                                               int M, int N, int K) {
    __shared__ float As[2][8][132];
    __shared__ float Bs[2][8][128];
    int t  = threadIdx.x;
    int tx = t & 15, ty = t >> 4;
    int m0 = blockIdx.x * 128, n0 = blockIdx.y * 128;

    int ar = t >> 1, ak = (t & 1) * 4;
    int br = t >> 5, bn = (t & 31) * 4;

    const float* Aptr = A + (size_t)(m0 + ar) * K + ak;
    const float* Bptr = B + (size_t)br * N + n0 + bn;

    float acc[8][8];
#pragma unroll
    for (int j = 0; j < 8; j++) {
        int n = (j < 4) ? tx * 4 + j : 64 + tx * 4 + (j - 4);
        float bv = bias ? bias[n0 + n] : 0.0f;
#pragma unroll
        for (int i = 0; i < 8; i++) acc[i][j] = bv;
    }

    float4 a_reg = *(const float4*)(Aptr);
    float4 b_reg = *(const float4*)(Bptr);
    As[0][ak + 0][ar] = a_reg.x;
    As[0][ak + 1][ar] = a_reg.y;
    As[0][ak + 2][ar] = a_reg.z;
    As[0][ak + 3][ar] = a_reg.w;
    *(float4*)(&Bs[0][br][bn]) = b_reg;
    __syncthreads();

    int nc = K / 8, buf = 0;
    for (int c = 0; c < nc; c++) {
        if (c + 1 < nc) {
            a_reg = *(const float4*)(Aptr + (c + 1) * 8);
            b_reg = *(const float4*)(Bptr + (size_t)(c + 1) * 8 * N);
        }
#pragma unroll
        for (int kk = 0; kk < 8; kk++) {
            float4 a0 = *(const float4*)(&As[buf][kk][ty * 4]);
            float4 a1 = *(const float4*)(&As[buf][kk][64 + ty * 4]);
            float4 b0 = *(const float4*)(&Bs[buf][kk][tx * 4]);
            float4 b1 = *(const float4*)(&Bs[buf][kk][64 + tx * 4]);
            float av[8] = {a0.x, a0.y, a0.z, a0.w, a1.x, a1.y, a1.z, a1.w};
            float bv[8] = {b0.x, b0.y, b0.z, b0.w, b1.x, b1.y, b1.z, b1.w};
#pragma unroll
            for (int i = 0; i < 8; i++)
#pragma unroll
                for (int j = 0; j < 8; j++) acc[i][j] += av[i] * bv[j];
        }
        if (c + 1 < nc) {
            int nb = buf ^ 1;
            As[nb][ak + 0][ar] = a_reg.x;
            As[nb][ak + 1][ar] = a_reg.y;
            As[nb][ak + 2][ar] = a_reg.z;
            As[nb][ak + 3][ar] = a_reg.w;
            *(float4*)(&Bs[nb][br][bn]) = b_reg;
        }
        __syncthreads();
        buf ^= 1;
    }

#pragma unroll
    for (int i = 0; i < 8; i++) {
        int m = m0 + ((i < 4) ? ty * 4 + i : 64 + ty * 4 + (i - 4));
        float4 o0 = make_float4(acc[i][0], acc[i][1], acc[i][2], acc[i][3]);
        float4 o1 = make_float4(acc[i][4], acc[i][5], acc[i][6], acc[i][7]);
        *(float4*)(C + (size_t)m * N + n0 + tx * 4) = o0;
        *(float4*)(C + (size_t)m * N + n0 + 64 + tx * 4) = o1;
    }
}

// ============== split-K skinny GEMM, double-buffered ==============
// 64x64 tile, 4x4 microtile, grid (M/64, N/64, KSPLIT).
template <int KLEN>
__global__ void __launch_bounds__(256) gemm64s(const float* __restrict__ A, int lda,
                                               const float* __restrict__ B,
                                               float* __restrict__ Cpart,
                                               int M, int N) {
    __shared__ __align__(16) float As[2][16][68];
    __shared__ __align__(16) float Bs[2][16][64];
    constexpr int NC = KLEN / 16;
    int t  = threadIdx.x;
    int tx = t & 15, ty = t >> 4;
    int m0 = blockIdx.x * 64, n0 = blockIdx.y * 64;
    int kbase = blockIdx.z * KLEN;

    float acc[4][4];
#pragma unroll
    for (int i = 0; i < 4; i++)
#pragma unroll
        for (int j = 0; j < 4; j++) acc[i][j] = 0.0f;

    int arow = t >> 2, akq = (t & 3) * 4;
    int bk = t >> 4, bn = (t & 15) * 4;

    const float* Aptr = A + (size_t)(m0 + arow) * lda + kbase + akq;
    const float* Bptr = B + (size_t)(kbase + bk) * N + n0 + bn;

    float4 av = *(const float4*)(Aptr);
    float4 bv = *(const float4*)(Bptr);
    As[0][akq + 0][arow] = av.x;
    As[0][akq + 1][arow] = av.y;
    As[0][akq + 2][arow] = av.z;
    As[0][akq + 3][arow] = av.w;
    *(float4*)(&Bs[0][bk][bn]) = bv;
    __syncthreads();

    int buf = 0;
#pragma unroll
    for (int c = 0; c < NC; c++) {
        if (c + 1 < NC) {
            av = *(const float4*)(Aptr + (c + 1) * 16);
            bv = *(const float4*)(Bptr + (size_t)(c + 1) * 16 * N);
        }
#pragma unroll
        for (int kk = 0; kk < 16; kk++) {
            float4 a = *(const float4*)(&As[buf][kk][ty * 4]);
            float4 b = *(const float4*)(&Bs[buf][kk][tx * 4]);
            float aa[4] = {a.x, a.y, a.z, a.w};
            float bb[4] = {b.x, b.y, b.z, b.w};
#pragma unroll
            for (int i = 0; i < 4; i++)
#pragma unroll
                for (int j = 0; j < 4; j++) acc[i][j] += aa[i] * bb[j];
        }
        if (c + 1 < NC) {
            int nb = buf ^ 1;
            As[nb][akq + 0][arow] = av.x;
            As[nb][akq + 1][arow] = av.y;
            As[nb][akq + 2][arow] = av.z;
            As[nb][akq + 3][arow] = av.w;
            *(float4*)(&Bs[nb][bk][bn]) = bv;
        }
        __syncthreads();
        buf ^= 1;
    }

    float* Cp = Cpart + (size_t)blockIdx.z * M * N;
#pragma unroll
    for (int i = 0; i < 4; i++) {
        float4 o = make_float4(acc[i][0], acc[i][1], acc[i][2], acc[i][3]);
        *(float4*)(Cp + (size_t)(m0 + ty * 4 + i) * N + n0 + tx * 4) = o;
    }
}

// ---------------- one-time setup ----------------
__global__ void build_wcat(const float* __restrict__ W_ih, const float* __restrict__ W_hh,
                           const float* __restrict__ b_ih, const float* __restrict__ b_hh) {
    int idx = blockIdx.x * 256 + threadIdx.x;
    if (idx < KPAD * HID) {
        int k = idx / HID, h = idx - k * HID;
        float w = 0.0f;
        if (k < 576)       w = W_ih[(size_t)h * 576 + k];
        else if (k < KCAT) w = W_hh[(size_t)h * 512 + (k - 576)];
        g_WcatT[idx] = w;
    }
    if (idx < HID) g_bsum[idx] = b_ih[idx] + b_hh[idx];
}

__global__ void init_state(const float* __restrict__ h0, const float* __restrict__ x0) {
    int i = blockIdx.x * 256 + threadIdx.x;
    if (i < BATCH * HID) g_h0buf[i] = h0[i];
    if (i < BATCH * OUTD) g_x0buf[i] = x0[i];
    if (i < BATCH * (KPAD - KCAT))
        g_rin[(i >> 6) * KPAD + KCAT + (i & 63)] = 0.0f;
}

// ============== fused flash-style: q-reduce + score + online-softmax + ctx + pack ==========
// grid 256 (one block per b), 512 threads (16 warps, each owns 16 s-rows).
__global__ void __launch_bounds__(512, 2) scorectx(const float* __restrict__ v,
                                                   const float* __restrict__ enc,
                                                   const float* __restrict__ xin,
                                                   const float* __restrict__ hin) {
    __shared__ __align__(16) float sq[HID];
    __shared__ __align__(16) float sv[HID];
    __shared__ __align__(16) float ctxp[16][HID];   // 32 KB warp partials
    __shared__ float wm[16], wl[16], walpha[16], sinvL;

    int b = blockIdx.x, t = threadIdx.x;
    int warp = t >> 5, lane = t & 31;

    // q = deterministic sum of 8 split-K partials
    {
        float s = 0.0f;
#pragma unroll
        for (int ks = 0; ks < KSPLIT; ks++)
            s += g_qpart[(size_t)ks * BATCH * HID + b * HID + t];
        sq[t] = s;
        sv[t] = v[t];
    }
    __syncthreads();

    const float4* q4 = (const float4*)sq;
    const float4* v4 = (const float4*)sv;

    float4 c0 = make_float4(0.f, 0.f, 0.f, 0.f), c1 = c0, c2 = c0, c3 = c0;
    float m = -3.4e38f, l = 0.0f;

    for (int i = 0; i < 16; i++) {
        int s = warp * 16 + i;
        const float4* Pr = (const float4*)(g_P + ((size_t)s * BATCH + b) * HID);
        const float4* Er = (const float4*)(enc + ((size_t)s * BATCH + b) * HID);
        float4 p0 = Pr[lane], p1 = Pr[32 + lane], p2 = Pr[64 + lane], p3 = Pr[96 + lane];
        float4 e0 = Er[lane], e1 = Er[32 + lane], e2 = Er[64 + lane], e3 = Er[96 + lane];
        float4 q0 = q4[lane], q1 = q4[32 + lane], q2 = q4[64 + lane], q3 = q4[96 + lane];
        float4 v0 = v4[lane], v1 = v4[32 + lane], v2 = v4[64 + lane], v3 = v4[96 + lane];

        float acc = fast_tanh(p0.x + q0.x) * v0.x + fast_tanh(p0.y + q0.y) * v0.y +
                    fast_tanh(p0.z + q0.z) * v0.z + fast_tanh(p0.w + q0.w) * v0.w;
        acc      += fast_tanh(p1.x + q1.x) * v1.x + fast_tanh(p1.y + q1.y) * v1.y +
                    fast_tanh(p1.z + q1.z) * v1.z + fast_tanh(p1.w + q1.w) * v1.w;
        acc      += fast_tanh(p2.x + q2.x) * v2.x + fast_tanh(p2.y + q2.y) * v2.y +
                    fast_tanh(p2.z + q2.z) * v2.z + fast_tanh(p2.w + q2.w) * v2.w;
        acc      += fast_tanh(p3.x + q3.x) * v3.x + fast_tanh(p3.y + q3.y) * v3.y +
                    fast_tanh(p3.z + q3.z) * v3.z + fast_tanh(p3.w + q3.w) * v3.w;
#pragma unroll
        for (int o = 16; o; o >>= 1) acc += __shfl_xor_sync(0xffffffffu, acc, o);

        // online softmax update (deterministic, fixed order)
        float mnew = fmaxf(m, acc);
        float resc = __expf(m - mnew);     // 0 on first iteration (m = -inf)
        float ws   = __expf(acc - mnew);
        l = l * resc + ws;
        c0.x = c0.x * resc + ws * e0.x;  c0.y = c0.y * resc + ws * e0.y;
        c0.z = c0.z * resc + ws * e0.z;  c0.w = c0.w * resc + ws * e0.w;
        c1.x = c1.x * resc + ws * e1.x;  c1.y = c1.y * resc + ws * e1.y;
        c1.z = c1.z * resc + ws * e1.z;  c1.w = c1.w * resc + ws * e1.w;
        c2.x = c2.x * resc + ws * e2.x;  c2.y = c2.y * resc + ws * e2.y;
        c2.z = c2.z * resc + ws * e2.z;  c2.w = c2.w * resc + ws * e2.w;
        c3.x = c3.x * resc + ws * e3.x;  c3.y = c3.y * resc + ws * e3.y;
        c3.z = c3.z * resc + ws * e3.z;  c3.w = c3.w * resc + ws * e3.w;
        m = mnew;
    }

    if (lane == 0) { wm[warp] = m; wl[warp] = l; }
    float4* cp = (float4*)ctxp[warp];
    cp[lane] = c0; cp[32 + lane] = c1; cp[64 + lane] = c2; cp[96 + lane] = c3;
    __syncthreads();

    // combine 16 warp-partials
    if (t < 16) {
        float mw = wm[t];
        float M = mw;
#pragma unroll
        for (int o = 8; o; o >>= 1) M = fmaxf(M, __shfl_xor_sync(0xffffu, M, o));
        float a = __expf(mw - M);
        float Lp = wl[t] * a;
#pragma unroll
        for (int o = 8; o; o >>= 1) Lp += __shfl_xor_sync(0xffffu, Lp, o);
        walpha[t] = a;
        if (t == 0) sinvL = __fdividef(1.0f, Lp);
    }
    __syncthreads();

    // ctx[h] and pack rnn_in = [x | ctx | h]
    {
        float c = 0.0f;
#pragma unroll
        for (int w = 0; w < 16; w++) c += walpha[w] * ctxp[w][t];
        g_rin[b * KPAD + OUTD + t] = c * sinvL;
        g_rin[b * KPAD + OUTD + HID + t] = hin[b * HID + t];
    }
    if (t < OUTD) g_rin[b * KPAD + t] = xin[b * OUTD + t];
}

// ============== reduce rnn partials + tanh + output head + argmax + one-hot ==============
__global__ void __launch_bounds__(256) outred(const float* __restrict__ Wo,
                                              const float* __restrict__ bo,
                                              float* __restrict__ hout,
                                              float* __restrict__ dout,
                                              float* __restrict__ xnext, int step) {
    int b = blockIdx.x, t = threadIdx.x;
    __shared__ __align__(16) float sh[HID];
    __shared__ float so[OUTD];
    __shared__ int sbest;

    float s0 = g_bsum[t], s1 = g_bsum[t + 256];
#pragma unroll
    for (int ks = 0; ks < KSPLIT; ks++) {
        const float* p = g_rnnpart + (size_t)ks * BATCH * HID + b * HID;
        s0 += p[t];
        s1 += p[t + 256];
    }
    float v0 = fast_tanh(s0), v1 = fast_tanh(s1);
    sh[t] = v0;
    sh[t + 256] = v1;
    hout[b * HID + t] = v0;
    hout[b * HID + t + 256] = v1;
    __syncthreads();

    int warp = t >> 5, lane = t & 31;
    const float4* h4 = (const float4*)sh;
    for (int o = warp; o < OUTD; o += 8) {
        const float4* w4 = (const float4*)(Wo + (size_t)o * HID);
        float acc = 0.0f;
#pragma unroll
        for (int i = 0; i < 4; i++) {
            float4 w = w4[i * 32 + lane], h = h4[i * 32 + lane];
            acc += w.x * h.x + w.y * h.y + w.z * h.z + w.w * h.w;
        }
#pragma unroll
        for (int off = 16; off; off >>= 1) acc += __shfl_xor_sync(0xffffffffu, acc, off);
        if (lane == 0) so[o] = acc + bo[o];
    }
    __syncthreads();
    if (t < OUTD) dout[((size_t)b * OUTD + t) * NSTEP + step] = so[t];
    if (t == 0) {
        float best = so[0];
        int bi = 0;
#pragma unroll
        for (int o = 1; o < OUTD; o++)
            if (so[o] > best) { best = so[o]; bi = o; }
        sbest = bi;
    }
    __syncthreads();
    if (t < OUTD) xnext[b * OUTD + t] = (t == sbest) ? 1.0f : 0.0f;
}

// ---------------- launch ----------------
extern "C" void kernel_launch(void* const* d_in, const int* in_sizes, int n_in,
                              void* d_out, int out_size) {
    const float* sos = (const float*)d_in[0];
    const float* h0  = (const float*)d_in[1];
    const float* enc = (const float*)d_in[2];
    const float* Wa  = (const float*)d_in[3];
    const float* ba  = (const float*)d_in[4];
    const float* v   = (const float*)d_in[5];
    const float* Wih = (const float*)d_in[6];
    const float* bih = (const float*)d_in[7];
    const float* Whh = (const float*)d_in[8];
    const float* bhh = (const float*)d_in[9];
    const float* Wo  = (const float*)d_in[10];
    const float* bo  = (const float*)d_in[11];
    float* out = (float*)d_out;

    float *pP, *pqp, *prp, *pr, *pW, *ph[2], *px[2];
    cudaGetSymbolAddress((void**)&pP,  g_P);
    cudaGetSymbolAddress((void**)&pqp, g_qpart);
    cudaGetSymbolAddress((void**)&prp, g_rnnpart);
    cudaGetSymbolAddress((void**)&pr,  g_rin);
    cudaGetSymbolAddress((void**)&pW,  g_WcatT);
    cudaGetSymbolAddress((void**)&ph[0], g_h0buf);
    cudaGetSymbolAddress((void**)&ph[1], g_h1buf);
    cudaGetSymbolAddress((void**)&px[0], g_x0buf);
    cudaGetSymbolAddress((void**)&px[1], g_x1buf);

    init_state<<<512, 256>>>(h0, sos);
    build_wcat<<<(KPAD * HID + 255) / 256, 256>>>(Wih, Whh, bih, bhh);
    gemm128<<<dim3(S_LEN * BATCH / 128, HID / 128), 256>>>(enc, Wa + 512 * HID, ba, pP,
                                                           S_LEN * BATCH, HID, HID);

    for (int t = 0; t < NSTEP; t++) {
        int cur = t & 1, nxt = cur ^ 1;
        gemm64s<64><<<dim3(BATCH / 64, HID / 64, KSPLIT), 256>>>(ph[cur], HID, Wa, pqp,
                                                                 BATCH, HID);
        scorectx<<<BATCH, 512>>>(v, enc, px[cur], ph[cur]);
        gemm64s<144><<<dim3(BATCH / 64, HID / 64, KSPLIT), 256>>>(pr, KPAD, pW, prp,
                                                                  BATCH, HID);
        outred<<<BATCH, 256>>>(Wo, bo, ph[nxt], out, px[nxt], t);
    }
}